// round 5
// baseline (speedup 1.0000x reference)
#include <cuda_runtime.h>
#include <cuda_bf16.h>
#include <cstdint>
#include <math.h>

// Problem constants
#define BB   2
#define SS   2048
#define DD   1024
#define HH   16
#define DKK  64
#define DFF  4096
#define ROWS (BB*SS)          // 4096
#define EPS  1e-6f

// ---------------- scratch (static device memory; no allocs allowed) ----------
__device__ float g_xn [ (size_t)ROWS * DD ];
__device__ float g_q  [ (size_t)ROWS * DD ];
__device__ float g_k  [ (size_t)ROWS * DD ];
__device__ float g_v  [ (size_t)ROWS * DD ];
__device__ float g_ctx[ (size_t)ROWS * DD ];
__device__ float g_x1 [ (size_t)ROWS * DD ];
__device__ float g_h  [ (size_t)ROWS * DFF ];

// ---------------- helpers ----------------------------------------------------
__device__ __forceinline__ float to_tf32(float x) {
    unsigned int u;
    asm("cvt.rna.tf32.f32 %0, %1;" : "=r"(u) : "f"(x));
    return __uint_as_float(u);
}

__device__ __forceinline__ void mma_tf32(float* c, const unsigned int* a, const unsigned int* b) {
    asm volatile(
        "mma.sync.aligned.m16n8k8.row.col.f32.tf32.tf32.f32 "
        "{%0,%1,%2,%3}, {%4,%5,%6,%7}, {%8,%9}, {%0,%1,%2,%3};\n"
        : "+f"(c[0]), "+f"(c[1]), "+f"(c[2]), "+f"(c[3])
        : "r"(a[0]), "r"(a[1]), "r"(a[2]), "r"(a[3]),
          "r"(b[0]), "r"(b[1]));
}

__device__ __forceinline__ void cp_async16(void* smem_dst, const void* gsrc) {
    unsigned int saddr = (unsigned int)__cvta_generic_to_shared(smem_dst);
    asm volatile("cp.async.cg.shared.global [%0], [%1], 16;\n"
                 :: "r"(saddr), "l"(gsrc));
}
__device__ __forceinline__ void cp_commit() {
    asm volatile("cp.async.commit_group;\n");
}
template<int N>
__device__ __forceinline__ void cp_wait() {
    asm volatile("cp.async.wait_group %0;\n" :: "n"(N));
}

// ---------------- LayerNorm: one block per row, 256 threads, float4 ---------
__global__ void layernorm_kernel(const float* __restrict__ X,
                                 const float* __restrict__ gamma,
                                 const float* __restrict__ beta,
                                 float* __restrict__ Y)
{
    __shared__ float red[8];
    const int row = blockIdx.x;
    const int tid = threadIdx.x;
    const float* x = X + (size_t)row * DD + tid * 4;

    float4 xv = *(const float4*)x;

    float s = xv.x + xv.y + xv.z + xv.w;
    #pragma unroll
    for (int o = 16; o; o >>= 1) s += __shfl_xor_sync(0xffffffffu, s, o);
    if ((tid & 31) == 0) red[tid >> 5] = s;
    __syncthreads();
    float tot = red[0] + red[1] + red[2] + red[3] + red[4] + red[5] + red[6] + red[7];
    float mean = tot * (1.0f / DD);

    float dx0 = xv.x - mean, dx1 = xv.y - mean, dx2 = xv.z - mean, dx3 = xv.w - mean;
    float sq = dx0*dx0 + dx1*dx1 + dx2*dx2 + dx3*dx3;
    __syncthreads();
    #pragma unroll
    for (int o = 16; o; o >>= 1) sq += __shfl_xor_sync(0xffffffffu, sq, o);
    if ((tid & 31) == 0) red[tid >> 5] = sq;
    __syncthreads();
    float tot2 = red[0] + red[1] + red[2] + red[3] + red[4] + red[5] + red[6] + red[7];
    float stdv = sqrtf(tot2 * (1.0f / DD));
    float inv  = 1.0f / (stdv + EPS);

    const int c = tid * 4;
    float4 g4 = *(const float4*)(gamma + c);
    float4 b4 = *(const float4*)(beta  + c);
    float4 o4;
    o4.x = g4.x * dx0 * inv + b4.x;
    o4.y = g4.y * dx1 * inv + b4.y;
    o4.z = g4.z * dx2 * inv + b4.z;
    o4.w = g4.w * dx3 * inv + b4.w;
    *(float4*)(Y + (size_t)row * DD + c) = o4;
}

// ---------------- TF32 GEMM v2: cp.async + 64x64 warp tiles -----------------
// BM=BN=128, BK=16, 128 threads (4 warps), warp tile 64x64 (4x8 mma tiles).
// Double-buffered cp.async pipeline. blockIdx.z selects among 3 (B,C) pairs
// (for the fused QKV launch; single GEMMs pass the same pointer 3x).
// Raw fp32 bits fed to tf32 mma (HW truncation) — no cvt in the load path.
#define AST 20     // As row stride: banks (20g+t)&31 all distinct, 80B 16B-aligned
#define BST 136    // Bs row stride: banks (8t+g)&31 all distinct, 544B 16B-aligned

__global__ void __launch_bounds__(128) gemm_tf32_v2(
    const float* __restrict__ A,
    const float* __restrict__ B0, const float* __restrict__ B1, const float* __restrict__ B2,
    float* __restrict__ C0, float* __restrict__ C1, float* __restrict__ C2,
    const float* __restrict__ bias,
    const float* __restrict__ res,
    int M, int N, int K, int relu)
{
    __shared__ float As[2][128][AST];
    __shared__ float Bs[2][16][BST];

    const float* B = (blockIdx.z == 0) ? B0 : (blockIdx.z == 1) ? B1 : B2;
    float*       C = (blockIdx.z == 0) ? C0 : (blockIdx.z == 1) ? C1 : C2;

    const int tid  = threadIdx.x;
    const int lane = tid & 31, warp = tid >> 5;
    const int wm = warp & 1;          // m half (64 rows)
    const int wn = warp >> 1;         // n half (64 cols)
    const int g = lane >> 2, t = lane & 3;
    const int bx = blockIdx.x, by = blockIdx.y;

    // loader mapping
    const int arow   = tid >> 2;          // 0..31 (+32r)
    const int akoff  = (tid & 3) * 4;     // 0,4,8,12
    const int brow   = tid >> 3;          // 0..15
    const int bcoff  = (tid & 7) * 16;    // 0..112

    const float* Ab = A + (size_t)(by * 128) * K;
    const float* Bb = B + bx * 128;

    float acc[4][8][4];
    #pragma unroll
    for (int i = 0; i < 4; i++)
        #pragma unroll
        for (int j = 0; j < 8; j++)
            #pragma unroll
            for (int e = 0; e < 4; e++) acc[i][j][e] = 0.0f;

    // stage loader
    auto load_stage = [&](int st, int k0) {
        #pragma unroll
        for (int r = 0; r < 4; r++) {
            const int row = arow + r * 32;
            cp_async16(&As[st][row][akoff], Ab + (size_t)row * K + k0 + akoff);
        }
        const float* bsrc = Bb + (size_t)(k0 + brow) * N + bcoff;
        #pragma unroll
        for (int c = 0; c < 4; c++)
            cp_async16(&Bs[st][brow][bcoff + c * 4], bsrc + c * 4);
    };

    load_stage(0, 0);
    cp_commit();

    const int nIter = K >> 4;
    for (int it = 0; it < nIter; ++it) {
        const int cur = it & 1;
        if (it + 1 < nIter) {
            load_stage(cur ^ 1, (it + 1) * 16);
            cp_commit();
            cp_wait<1>();
        } else {
            cp_wait<0>();
        }
        __syncthreads();

        #pragma unroll
        for (int ks = 0; ks < 2; ks++) {
            const int k0 = ks * 8;
            unsigned int af[4][4], bf[8][2];
            #pragma unroll
            for (int i = 0; i < 4; i++) {
                const int m0 = wm * 64 + i * 16;
                af[i][0] = __float_as_uint(As[cur][m0 + g    ][k0 + t    ]);
                af[i][1] = __float_as_uint(As[cur][m0 + g + 8][k0 + t    ]);
                af[i][2] = __float_as_uint(As[cur][m0 + g    ][k0 + t + 4]);
                af[i][3] = __float_as_uint(As[cur][m0 + g + 8][k0 + t + 4]);
            }
            #pragma unroll
            for (int j = 0; j < 8; j++) {
                const int n0 = wn * 64 + j * 8;
                bf[j][0] = __float_as_uint(Bs[cur][k0 + t    ][n0 + g]);
                bf[j][1] = __float_as_uint(Bs[cur][k0 + t + 4][n0 + g]);
            }
            #pragma unroll
            for (int i = 0; i < 4; i++)
                #pragma unroll
                for (int j = 0; j < 8; j++)
                    mma_tf32(acc[i][j], af[i], bf[j]);
        }
        __syncthreads();
    }

    // epilogue
    #pragma unroll
    for (int i = 0; i < 4; i++) {
        #pragma unroll
        for (int j = 0; j < 8; j++) {
            const int row0 = by * 128 + wm * 64 + i * 16 + g;
            const int col  = bx * 128 + wn * 64 + j * 8 + t * 2;
            float v0 = acc[i][j][0], v1 = acc[i][j][1];
            float v2 = acc[i][j][2], v3 = acc[i][j][3];
            if (bias) {
                float b0v = bias[col], b1v = bias[col + 1];
                v0 += b0v; v1 += b1v; v2 += b0v; v3 += b1v;
            }
            if (relu) {
                v0 = fmaxf(v0, 0.0f); v1 = fmaxf(v1, 0.0f);
                v2 = fmaxf(v2, 0.0f); v3 = fmaxf(v3, 0.0f);
            }
            size_t p0 = (size_t)row0 * N + col;
            size_t p1 = (size_t)(row0 + 8) * N + col;
            if (res) {
                float2 r0 = *(const float2*)(res + p0);
                float2 r1 = *(const float2*)(res + p1);
                v0 += r0.x; v1 += r0.y; v2 += r1.x; v3 += r1.y;
            }
            *(float2*)(C + p0) = make_float2(v0, v1);
            *(float2*)(C + p1) = make_float2(v2, v3);
        }
    }
}

// ---------------- Flash attention, tf32 tensor cores (unchanged R4) ---------
#define FBK 32

__global__ void __launch_bounds__(128) flash_attn_tc(const float* __restrict__ Q,
                                                     const float* __restrict__ K,
                                                     const float* __restrict__ V,
                                                     float* __restrict__ O)
{
    __shared__ float Qs[64][68];
    __shared__ float Ks[FBK][68];
    __shared__ float Vs[FBK][72];
    __shared__ float Ps[64][36];

    const int b = blockIdx.z, h = blockIdx.y;
    const int q0 = blockIdx.x * 64;
    const int tid = threadIdx.x, lane = tid & 31, warp = tid >> 5;
    const int g = lane >> 2, t = lane & 3;
    const int mrow = warp * 16;

    const float* Qb = Q + ((size_t)b * SS + q0) * DD + h * DKK;
    const float* Kb = K + (size_t)b * SS * DD + h * DKK;
    const float* Vb = V + (size_t)b * SS * DD + h * DKK;

    for (int i = tid; i < 64 * 16; i += 128) {
        int r = i >> 4, c4 = (i & 15) * 4;
        float4 qv = *(const float4*)(Qb + (size_t)r * DD + c4);
        Qs[r][c4+0] = to_tf32(qv.x);
        Qs[r][c4+1] = to_tf32(qv.y);
        Qs[r][c4+2] = to_tf32(qv.z);
        Qs[r][c4+3] = to_tf32(qv.w);
    }

    float m0v = -1e30f, m1v = -1e30f, l0 = 0.0f, l1 = 0.0f;
    float acc[8][4];
    #pragma unroll
    for (int n = 0; n < 8; n++)
        #pragma unroll
        for (int e = 0; e < 4; e++) acc[n][e] = 0.0f;

    for (int k0 = 0; k0 < SS; k0 += FBK) {
        __syncthreads();
        for (int i = tid; i < FBK * 16; i += 128) {
            int r = i >> 4, c4 = (i & 15) * 4;
            float4 kv = *(const float4*)(Kb + (size_t)(k0 + r) * DD + c4);
            Ks[r][c4+0] = to_tf32(kv.x);
            Ks[r][c4+1] = to_tf32(kv.y);
            Ks[r][c4+2] = to_tf32(kv.z);
            Ks[r][c4+3] = to_tf32(kv.w);
            float4 vv = *(const float4*)(Vb + (size_t)(k0 + r) * DD + c4);
            Vs[r][c4+0] = to_tf32(vv.x);
            Vs[r][c4+1] = to_tf32(vv.y);
            Vs[r][c4+2] = to_tf32(vv.z);
            Vs[r][c4+3] = to_tf32(vv.w);
        }
        __syncthreads();

        float sf[4][4];
        #pragma unroll
        for (int j = 0; j < 4; j++)
            #pragma unroll
            for (int e = 0; e < 4; e++) sf[j][e] = 0.0f;

        #pragma unroll
        for (int kc = 0; kc < 8; kc++) {
            const int kk = kc * 8;
            unsigned int af[4];
            af[0] = __float_as_uint(Qs[mrow + g    ][kk + t    ]);
            af[1] = __float_as_uint(Qs[mrow + g + 8][kk + t    ]);
            af[2] = __float_as_uint(Qs[mrow + g    ][kk + t + 4]);
            af[3] = __float_as_uint(Qs[mrow + g + 8][kk + t + 4]);
            #pragma unroll
            for (int j = 0; j < 4; j++) {
                unsigned int bf[2];
                bf[0] = __float_as_uint(Ks[j * 8 + g][kk + t    ]);
                bf[1] = __float_as_uint(Ks[j * 8 + g][kk + t + 4]);
                mma_tf32(sf[j], af, bf);
            }
        }

        float rmax0 = -1e30f, rmax1 = -1e30f;
        #pragma unroll
        for (int j = 0; j < 4; j++) {
            sf[j][0] *= 0.125f; sf[j][1] *= 0.125f;
            sf[j][2] *= 0.125f; sf[j][3] *= 0.125f;
            rmax0 = fmaxf(rmax0, fmaxf(sf[j][0], sf[j][1]));
            rmax1 = fmaxf(rmax1, fmaxf(sf[j][2], sf[j][3]));
        }
        rmax0 = fmaxf(rmax0, __shfl_xor_sync(0xffffffffu, rmax0, 1));
        rmax0 = fmaxf(rmax0, __shfl_xor_sync(0xffffffffu, rmax0, 2));
        rmax1 = fmaxf(rmax1, __shfl_xor_sync(0xffffffffu, rmax1, 1));
        rmax1 = fmaxf(rmax1, __shfl_xor_sync(0xffffffffu, rmax1, 2));

        float mn0 = fmaxf(m0v, rmax0), mn1 = fmaxf(m1v, rmax1);
        float c0 = __expf(m0v - mn0), c1 = __expf(m1v - mn1);
        m0v = mn0; m1v = mn1;

        float ps0 = 0.0f, ps1 = 0.0f;
        #pragma unroll
        for (int j = 0; j < 4; j++) {
            float p00 = __expf(sf[j][0] - mn0);
            float p01 = __expf(sf[j][1] - mn0);
            float p10 = __expf(sf[j][2] - mn1);
            float p11 = __expf(sf[j][3] - mn1);
            ps0 += p00 + p01;
            ps1 += p10 + p11;
            *(float2*)&Ps[mrow + g    ][j * 8 + t * 2] = make_float2(to_tf32(p00), to_tf32(p01));
            *(float2*)&Ps[mrow + g + 8][j * 8 + t * 2] = make_float2(to_tf32(p10), to_tf32(p11));
        }
        ps0 += __shfl_xor_sync(0xffffffffu, ps0, 1);
        ps0 += __shfl_xor_sync(0xffffffffu, ps0, 2);
        ps1 += __shfl_xor_sync(0xffffffffu, ps1, 1);
        ps1 += __shfl_xor_sync(0xffffffffu, ps1, 2);
        l0 = l0 * c0 + ps0;
        l1 = l1 * c1 + ps1;

        #pragma unroll
        for (int n = 0; n < 8; n++) {
            acc[n][0] *= c0; acc[n][1] *= c0;
            acc[n][2] *= c1; acc[n][3] *= c1;
        }
        __syncwarp();

        #pragma unroll
        for (int kc = 0; kc < 4; kc++) {
            const int kk = kc * 8;
            unsigned int af[4];
            af[0] = __float_as_uint(Ps[mrow + g    ][kk + t    ]);
            af[1] = __float_as_uint(Ps[mrow + g + 8][kk + t    ]);
            af[2] = __float_as_uint(Ps[mrow + g    ][kk + t + 4]);
            af[3] = __float_as_uint(Ps[mrow + g + 8][kk + t + 4]);
            #pragma unroll
            for (int n = 0; n < 8; n++) {
                unsigned int bf[2];
                bf[0] = __float_as_uint(Vs[kk + t    ][n * 8 + g]);
                bf[1] = __float_as_uint(Vs[kk + t + 4][n * 8 + g]);
                mma_tf32(acc[n], af, bf);
            }
        }
    }

    const float inv0 = 1.0f / l0, inv1 = 1.0f / l1;
    const int row0 = q0 + mrow + g;
    #pragma unroll
    for (int n = 0; n < 8; n++) {
        const int col = h * DKK + n * 8 + t * 2;
        *(float2*)(O + ((size_t)b * SS + row0    ) * DD + col) =
            make_float2(acc[n][0] * inv0, acc[n][1] * inv0);
        *(float2*)(O + ((size_t)b * SS + row0 + 8) * DD + col) =
            make_float2(acc[n][2] * inv1, acc[n][3] * inv1);
    }
}

// ---------------- launch ----------------------------------------------------
extern "C" void kernel_launch(void* const* d_in, const int* in_sizes, int n_in,
                              void* d_out, int out_size)
{
    const float* x     = (const float*)d_in[0];
    // d_in[1] = mask (all ones in this problem)
    const float* wq    = (const float*)d_in[2];
    const float* wk    = (const float*)d_in[3];
    const float* wv    = (const float*)d_in[4];
    const float* wo    = (const float*)d_in[5];
    const float* w1    = (const float*)d_in[6];
    const float* b1    = (const float*)d_in[7];
    const float* w2    = (const float*)d_in[8];
    const float* b2    = (const float*)d_in[9];
    const float* ln1_a = (const float*)d_in[10];
    const float* ln1_b = (const float*)d_in[11];
    const float* ln2_a = (const float*)d_in[12];
    const float* ln2_b = (const float*)d_in[13];
    float* out = (float*)d_out;

    float *xn, *q, *k, *v, *ctx, *x1, *hb;
    cudaGetSymbolAddress((void**)&xn,  g_xn);
    cudaGetSymbolAddress((void**)&q,   g_q);
    cudaGetSymbolAddress((void**)&k,   g_k);
    cudaGetSymbolAddress((void**)&v,   g_v);
    cudaGetSymbolAddress((void**)&ctx, g_ctx);
    cudaGetSymbolAddress((void**)&x1,  g_x1);
    cudaGetSymbolAddress((void**)&hb,  g_h);

    // 1) ln1
    layernorm_kernel<<<ROWS, 256>>>(x, ln1_a, ln1_b, xn);
    // 2) Q/K/V projections fused into one launch (z picks weight/output)
    gemm_tf32_v2<<<dim3(DD / 128, ROWS / 128, 3), 128>>>(
        xn, wq, wk, wv, q, k, v, nullptr, nullptr, ROWS, DD, DD, 0);
    // 3) attention (tf32 tensor cores)
    flash_attn_tc<<<dim3(SS / 64, HH, BB), 128>>>(q, k, v, ctx);
    // 4) O projection + residual
    gemm_tf32_v2<<<dim3(DD / 128, ROWS / 128, 1), 128>>>(
        ctx, wo, wo, wo, x1, x1, x1, nullptr, x, ROWS, DD, DD, 0);
    // 5) ln2
    layernorm_kernel<<<ROWS, 256>>>(x1, ln2_a, ln2_b, xn);
    // 6) FFN1 + bias + relu
    gemm_tf32_v2<<<dim3(DFF / 128, ROWS / 128, 1), 128>>>(
        xn, w1, w1, w1, hb, hb, hb, b1, nullptr, ROWS, DFF, DD, 1);
    // 7) FFN2 + bias + residual -> out
    gemm_tf32_v2<<<dim3(DD / 128, ROWS / 128, 1), 128>>>(
        hb, w2, w2, w2, out, out, out, b2, x1, ROWS, DD, DFF, 0);
}

// round 6
// speedup vs baseline: 1.1632x; 1.1632x over previous
#include <cuda_runtime.h>
#include <cuda_bf16.h>
#include <cstdint>
#include <math.h>

// Problem constants
#define BB   2
#define SS   2048
#define DD   1024
#define HH   16
#define DKK  64
#define DFF  4096
#define ROWS (BB*SS)          // 4096
#define EPS  1e-6f

// ---------------- scratch (static device memory; no allocs allowed) ----------
__device__ float g_xn [ (size_t)ROWS * DD ];
__device__ float g_q  [ (size_t)ROWS * DD ];
__device__ float g_k  [ (size_t)ROWS * DD ];
__device__ float g_v  [ (size_t)ROWS * DD ];
__device__ float g_ctx[ (size_t)ROWS * DD ];
__device__ float g_x1 [ (size_t)ROWS * DD ];
__device__ float g_h  [ (size_t)ROWS * DFF ];

// ---------------- helpers ----------------------------------------------------
__device__ __forceinline__ float to_tf32(float x) {
    unsigned int u;
    asm("cvt.rna.tf32.f32 %0, %1;" : "=r"(u) : "f"(x));
    return __uint_as_float(u);
}

__device__ __forceinline__ void mma_tf32(float* c, const unsigned int* a, const unsigned int* b) {
    asm volatile(
        "mma.sync.aligned.m16n8k8.row.col.f32.tf32.tf32.f32 "
        "{%0,%1,%2,%3}, {%4,%5,%6,%7}, {%8,%9}, {%0,%1,%2,%3};\n"
        : "+f"(c[0]), "+f"(c[1]), "+f"(c[2]), "+f"(c[3])
        : "r"(a[0]), "r"(a[1]), "r"(a[2]), "r"(a[3]),
          "r"(b[0]), "r"(b[1]));
}

// ---------------- LayerNorm: one block per row, 256 threads, float4 ---------
__global__ void layernorm_kernel(const float* __restrict__ X,
                                 const float* __restrict__ gamma,
                                 const float* __restrict__ beta,
                                 float* __restrict__ Y)
{
    __shared__ float red[8];
    const int row = blockIdx.x;
    const int tid = threadIdx.x;
    const float* x = X + (size_t)row * DD + tid * 4;

    float4 xv = *(const float4*)x;

    float s = xv.x + xv.y + xv.z + xv.w;
    #pragma unroll
    for (int o = 16; o; o >>= 1) s += __shfl_xor_sync(0xffffffffu, s, o);
    if ((tid & 31) == 0) red[tid >> 5] = s;
    __syncthreads();
    float tot = red[0] + red[1] + red[2] + red[3] + red[4] + red[5] + red[6] + red[7];
    float mean = tot * (1.0f / DD);

    float dx0 = xv.x - mean, dx1 = xv.y - mean, dx2 = xv.z - mean, dx3 = xv.w - mean;
    float sq = dx0*dx0 + dx1*dx1 + dx2*dx2 + dx3*dx3;
    __syncthreads();
    #pragma unroll
    for (int o = 16; o; o >>= 1) sq += __shfl_xor_sync(0xffffffffu, sq, o);
    if ((tid & 31) == 0) red[tid >> 5] = sq;
    __syncthreads();
    float tot2 = red[0] + red[1] + red[2] + red[3] + red[4] + red[5] + red[6] + red[7];
    float stdv = sqrtf(tot2 * (1.0f / DD));
    float inv  = 1.0f / (stdv + EPS);

    const int c = tid * 4;
    float4 g4 = *(const float4*)(gamma + c);
    float4 b4 = *(const float4*)(beta  + c);
    float4 o4;
    o4.x = g4.x * dx0 * inv + b4.x;
    o4.y = g4.y * dx1 * inv + b4.y;
    o4.z = g4.z * dx2 * inv + b4.z;
    o4.w = g4.w * dx3 * inv + b4.w;
    *(float4*)(Y + (size_t)row * DD + c) = o4;
}

// ---------------- TF32 tensor-core GEMM (R4-proven config) ------------------
// BM=BN=128, BK=16, 256 threads (8 warps), warp tile 64x32 (2m x 4n).
// cvt.rna in the load path (accuracy), double-buffered smem, register prefetch.
// blockIdx.z selects among 3 (B,C) pairs for the fused QKV launch.
#define AST 20     // As row stride: banks (20g+t)&31 all distinct
#define BST 136    // Bs row stride: banks (8t+g)&31 all distinct

__global__ void gemm_tf32_kernel(
    const float* __restrict__ A,
    const float* __restrict__ B0, const float* __restrict__ B1, const float* __restrict__ B2,
    float* __restrict__ C0, float* __restrict__ C1, float* __restrict__ C2,
    const float* __restrict__ bias,
    const float* __restrict__ res,
    int M, int N, int K, int relu)
{
    __shared__ float As[2][128][AST];
    __shared__ float Bs[2][16][BST];

    const float* B = (blockIdx.z == 0) ? B0 : (blockIdx.z == 1) ? B1 : B2;
    float*       C = (blockIdx.z == 0) ? C0 : (blockIdx.z == 1) ? C1 : C2;

    const int tid  = threadIdx.x;
    const int lane = tid & 31, warp = tid >> 5;
    const int wm = warp & 1;
    const int wn = warp >> 1;
    const int g = lane >> 2, t = lane & 3;
    const int bx = blockIdx.x, by = blockIdx.y;

    const int arow = tid >> 2;
    const int acol = (tid & 3) * 4;
    const int brow = tid >> 4;
    const int bcol = (tid & 15) * 4;

    const float* Ap0 = A + (size_t)(by * 128 + arow) * K + acol;
    const float* Ap1 = Ap0 + (size_t)64 * K;
    const float* Bp  = B + (size_t)brow * N + bx * 128 + bcol;

    float acc[4][4][4];
    #pragma unroll
    for (int i = 0; i < 4; i++)
        #pragma unroll
        for (int j = 0; j < 4; j++)
            #pragma unroll
            for (int e = 0; e < 4; e++) acc[i][j][e] = 0.0f;

    {
        float4 a0 = *(const float4*)Ap0;
        float4 a1 = *(const float4*)Ap1;
        float4 b0 = *(const float4*)Bp;
        float4 b1 = *(const float4*)(Bp + 64);
        As[0][arow     ][acol+0] = to_tf32(a0.x);
        As[0][arow     ][acol+1] = to_tf32(a0.y);
        As[0][arow     ][acol+2] = to_tf32(a0.z);
        As[0][arow     ][acol+3] = to_tf32(a0.w);
        As[0][arow + 64][acol+0] = to_tf32(a1.x);
        As[0][arow + 64][acol+1] = to_tf32(a1.y);
        As[0][arow + 64][acol+2] = to_tf32(a1.z);
        As[0][arow + 64][acol+3] = to_tf32(a1.w);
        Bs[0][brow][bcol+0]      = to_tf32(b0.x);
        Bs[0][brow][bcol+1]      = to_tf32(b0.y);
        Bs[0][brow][bcol+2]      = to_tf32(b0.z);
        Bs[0][brow][bcol+3]      = to_tf32(b0.w);
        Bs[0][brow][bcol+64]     = to_tf32(b1.x);
        Bs[0][brow][bcol+65]     = to_tf32(b1.y);
        Bs[0][brow][bcol+66]     = to_tf32(b1.z);
        Bs[0][brow][bcol+67]     = to_tf32(b1.w);
    }
    __syncthreads();

    const int nIter = K >> 4;
    for (int it = 0; it < nIter; ++it) {
        const int cur = it & 1, nxt = cur ^ 1;

        float4 na0, na1, nb0, nb1;
        const bool pf = (it + 1 < nIter);
        if (pf) {
            const float* pa = Ap0 + (size_t)(it + 1) * 16;
            na0 = *(const float4*)pa;
            na1 = *(const float4*)(pa + (size_t)64 * K);
            const float* pb = Bp + (size_t)(it + 1) * 16 * N;
            nb0 = *(const float4*)pb;
            nb1 = *(const float4*)(pb + 64);
        }

        #pragma unroll
        for (int ks = 0; ks < 2; ks++) {
            const int k0 = ks * 8;
            unsigned int af[4][4], bf[4][2];
            #pragma unroll
            for (int i = 0; i < 4; i++) {
                const int m0 = wm * 64 + i * 16;
                af[i][0] = __float_as_uint(As[cur][m0 + g    ][k0 + t    ]);
                af[i][1] = __float_as_uint(As[cur][m0 + g + 8][k0 + t    ]);
                af[i][2] = __float_as_uint(As[cur][m0 + g    ][k0 + t + 4]);
                af[i][3] = __float_as_uint(As[cur][m0 + g + 8][k0 + t + 4]);
            }
            #pragma unroll
            for (int j = 0; j < 4; j++) {
                const int n0 = wn * 32 + j * 8;
                bf[j][0] = __float_as_uint(Bs[cur][k0 + t    ][n0 + g]);
                bf[j][1] = __float_as_uint(Bs[cur][k0 + t + 4][n0 + g]);
            }
            #pragma unroll
            for (int i = 0; i < 4; i++)
                #pragma unroll
                for (int j = 0; j < 4; j++)
                    mma_tf32(acc[i][j], af[i], bf[j]);
        }

        if (pf) {
            As[nxt][arow     ][acol+0] = to_tf32(na0.x);
            As[nxt][arow     ][acol+1] = to_tf32(na0.y);
            As[nxt][arow     ][acol+2] = to_tf32(na0.z);
            As[nxt][arow     ][acol+3] = to_tf32(na0.w);
            As[nxt][arow + 64][acol+0] = to_tf32(na1.x);
            As[nxt][arow + 64][acol+1] = to_tf32(na1.y);
            As[nxt][arow + 64][acol+2] = to_tf32(na1.z);
            As[nxt][arow + 64][acol+3] = to_tf32(na1.w);
            Bs[nxt][brow][bcol+0]      = to_tf32(nb0.x);
            Bs[nxt][brow][bcol+1]      = to_tf32(nb0.y);
            Bs[nxt][brow][bcol+2]      = to_tf32(nb0.z);
            Bs[nxt][brow][bcol+3]      = to_tf32(nb0.w);
            Bs[nxt][brow][bcol+64]     = to_tf32(nb1.x);
            Bs[nxt][brow][bcol+65]     = to_tf32(nb1.y);
            Bs[nxt][brow][bcol+66]     = to_tf32(nb1.z);
            Bs[nxt][brow][bcol+67]     = to_tf32(nb1.w);
        }
        __syncthreads();
    }

    #pragma unroll
    for (int i = 0; i < 4; i++) {
        #pragma unroll
        for (int j = 0; j < 4; j++) {
            const int row0 = by * 128 + wm * 64 + i * 16 + g;
            const int col  = bx * 128 + wn * 32 + j * 8 + t * 2;
            float v0 = acc[i][j][0], v1 = acc[i][j][1];
            float v2 = acc[i][j][2], v3 = acc[i][j][3];
            if (bias) {
                float b0v = bias[col], b1v = bias[col + 1];
                v0 += b0v; v1 += b1v; v2 += b0v; v3 += b1v;
            }
            if (relu) {
                v0 = fmaxf(v0, 0.0f); v1 = fmaxf(v1, 0.0f);
                v2 = fmaxf(v2, 0.0f); v3 = fmaxf(v3, 0.0f);
            }
            size_t p0 = (size_t)row0 * N + col;
            size_t p1 = (size_t)(row0 + 8) * N + col;
            if (res) {
                float2 r0 = *(const float2*)(res + p0);
                float2 r1 = *(const float2*)(res + p1);
                v0 += r0.x; v1 += r0.y; v2 += r1.x; v3 += r1.y;
            }
            *(float2*)(C + p0) = make_float2(v0, v1);
            *(float2*)(C + p1) = make_float2(v2, v3);
        }
    }
}

// ---------------- Flash attention, tf32 TC + register prefetch --------------
// BQ=64/CTA, 4 warps (one m16 tile each; softmax warp-local), keys in 32-tiles.
// Next K/V tile is LDG'd into registers BEFORE compute, STS'd after barrier.
// K/V fed raw to tf32 mma (HW truncation; error invisible post-softmax);
// Q and P stay cvt.rna-rounded.
#define FBK 32

__global__ void __launch_bounds__(128) flash_attn_tc(const float* __restrict__ Q,
                                                     const float* __restrict__ K,
                                                     const float* __restrict__ V,
                                                     float* __restrict__ O)
{
    __shared__ float Qs[64][68];
    __shared__ float Ks[FBK][68];
    __shared__ float Vs[FBK][72];
    __shared__ float Ps[64][36];

    const int b = blockIdx.z, h = blockIdx.y;
    const int q0 = blockIdx.x * 64;
    const int tid = threadIdx.x, lane = tid & 31, warp = tid >> 5;
    const int g = lane >> 2, t = lane & 3;
    const int mrow = warp * 16;

    const float* Qb = Q + ((size_t)b * SS + q0) * DD + h * DKK;
    const float* Kb = K + (size_t)b * SS * DD + h * DKK;
    const float* Vb = V + (size_t)b * SS * DD + h * DKK;

    // loader mapping: 4 float4 per thread per tile (FBK*16 / 128 = 4)
    int lr[4], lc[4];
    #pragma unroll
    for (int s = 0; s < 4; s++) {
        int i = tid + s * 128;
        lr[s] = i >> 4;
        lc[s] = (i & 15) * 4;
    }

    // load Q tile (64x64), rounded
    for (int i = tid; i < 64 * 16; i += 128) {
        int r = i >> 4, c4 = (i & 15) * 4;
        float4 qv = *(const float4*)(Qb + (size_t)r * DD + c4);
        Qs[r][c4+0] = to_tf32(qv.x);
        Qs[r][c4+1] = to_tf32(qv.y);
        Qs[r][c4+2] = to_tf32(qv.z);
        Qs[r][c4+3] = to_tf32(qv.w);
    }

    // prologue: tile 0 -> smem (raw bits)
    #pragma unroll
    for (int s = 0; s < 4; s++) {
        float4 kv = *(const float4*)(Kb + (size_t)lr[s] * DD + lc[s]);
        Ks[lr[s]][lc[s]+0] = kv.x; Ks[lr[s]][lc[s]+1] = kv.y;
        Ks[lr[s]][lc[s]+2] = kv.z; Ks[lr[s]][lc[s]+3] = kv.w;
        float4 vv = *(const float4*)(Vb + (size_t)lr[s] * DD + lc[s]);
        Vs[lr[s]][lc[s]+0] = vv.x; Vs[lr[s]][lc[s]+1] = vv.y;
        Vs[lr[s]][lc[s]+2] = vv.z; Vs[lr[s]][lc[s]+3] = vv.w;
    }

    float m0v = -1e30f, m1v = -1e30f, l0 = 0.0f, l1 = 0.0f;
    float acc[8][4];
    #pragma unroll
    for (int n = 0; n < 8; n++)
        #pragma unroll
        for (int e = 0; e < 4; e++) acc[n][e] = 0.0f;

    __syncthreads();

    for (int k0 = 0; k0 < SS; k0 += FBK) {
        const bool pf = (k0 + FBK < SS);
        float4 kreg[4], vreg[4];
        if (pf) {
            const float* Kn = Kb + (size_t)(k0 + FBK) * DD;
            const float* Vn = Vb + (size_t)(k0 + FBK) * DD;
            #pragma unroll
            for (int s = 0; s < 4; s++) {
                kreg[s] = *(const float4*)(Kn + (size_t)lr[s] * DD + lc[s]);
                vreg[s] = *(const float4*)(Vn + (size_t)lr[s] * DD + lc[s]);
            }
        }

        // ---- S = Q K^T for this warp's 16 rows x 32 keys ----
        float sf[4][4];
        #pragma unroll
        for (int j = 0; j < 4; j++)
            #pragma unroll
            for (int e = 0; e < 4; e++) sf[j][e] = 0.0f;

        #pragma unroll
        for (int kc = 0; kc < 8; kc++) {
            const int kk = kc * 8;
            unsigned int af[4];
            af[0] = __float_as_uint(Qs[mrow + g    ][kk + t    ]);
            af[1] = __float_as_uint(Qs[mrow + g + 8][kk + t    ]);
            af[2] = __float_as_uint(Qs[mrow + g    ][kk + t + 4]);
            af[3] = __float_as_uint(Qs[mrow + g + 8][kk + t + 4]);
            #pragma unroll
            for (int j = 0; j < 4; j++) {
                unsigned int bf[2];
                bf[0] = __float_as_uint(Ks[j * 8 + g][kk + t    ]);
                bf[1] = __float_as_uint(Ks[j * 8 + g][kk + t + 4]);
                mma_tf32(sf[j], af, bf);
            }
        }

        // ---- online softmax (warp-local; rows g and g+8) ----
        float rmax0 = -1e30f, rmax1 = -1e30f;
        #pragma unroll
        for (int j = 0; j < 4; j++) {
            sf[j][0] *= 0.125f; sf[j][1] *= 0.125f;
            sf[j][2] *= 0.125f; sf[j][3] *= 0.125f;
            rmax0 = fmaxf(rmax0, fmaxf(sf[j][0], sf[j][1]));
            rmax1 = fmaxf(rmax1, fmaxf(sf[j][2], sf[j][3]));
        }
        rmax0 = fmaxf(rmax0, __shfl_xor_sync(0xffffffffu, rmax0, 1));
        rmax0 = fmaxf(rmax0, __shfl_xor_sync(0xffffffffu, rmax0, 2));
        rmax1 = fmaxf(rmax1, __shfl_xor_sync(0xffffffffu, rmax1, 1));
        rmax1 = fmaxf(rmax1, __shfl_xor_sync(0xffffffffu, rmax1, 2));

        float mn0 = fmaxf(m0v, rmax0), mn1 = fmaxf(m1v, rmax1);
        float c0 = __expf(m0v - mn0), c1 = __expf(m1v - mn1);
        m0v = mn0; m1v = mn1;

        float ps0 = 0.0f, ps1 = 0.0f;
        #pragma unroll
        for (int j = 0; j < 4; j++) {
            float p00 = __expf(sf[j][0] - mn0);
            float p01 = __expf(sf[j][1] - mn0);
            float p10 = __expf(sf[j][2] - mn1);
            float p11 = __expf(sf[j][3] - mn1);
            ps0 += p00 + p01;
            ps1 += p10 + p11;
            *(float2*)&Ps[mrow + g    ][j * 8 + t * 2] = make_float2(to_tf32(p00), to_tf32(p01));
            *(float2*)&Ps[mrow + g + 8][j * 8 + t * 2] = make_float2(to_tf32(p10), to_tf32(p11));
        }
        ps0 += __shfl_xor_sync(0xffffffffu, ps0, 1);
        ps0 += __shfl_xor_sync(0xffffffffu, ps0, 2);
        ps1 += __shfl_xor_sync(0xffffffffu, ps1, 1);
        ps1 += __shfl_xor_sync(0xffffffffu, ps1, 2);
        l0 = l0 * c0 + ps0;
        l1 = l1 * c1 + ps1;

        #pragma unroll
        for (int n = 0; n < 8; n++) {
            acc[n][0] *= c0; acc[n][1] *= c0;
            acc[n][2] *= c1; acc[n][3] *= c1;
        }
        __syncwarp();   // P writes visible to this warp's fragment loads

        // ---- O += P V ----
        #pragma unroll
        for (int kc = 0; kc < 4; kc++) {
            const int kk = kc * 8;
            unsigned int af[4];
            af[0] = __float_as_uint(Ps[mrow + g    ][kk + t    ]);
            af[1] = __float_as_uint(Ps[mrow + g + 8][kk + t    ]);
            af[2] = __float_as_uint(Ps[mrow + g    ][kk + t + 4]);
            af[3] = __float_as_uint(Ps[mrow + g + 8][kk + t + 4]);
            #pragma unroll
            for (int n = 0; n < 8; n++) {
                unsigned int bf[2];
                bf[0] = __float_as_uint(Vs[kk + t    ][n * 8 + g]);
                bf[1] = __float_as_uint(Vs[kk + t + 4][n * 8 + g]);
                mma_tf32(acc[n], af, bf);
            }
        }

        __syncthreads();   // all consumers done with Ks/Vs
        if (pf) {
            #pragma unroll
            for (int s = 0; s < 4; s++) {
                Ks[lr[s]][lc[s]+0] = kreg[s].x; Ks[lr[s]][lc[s]+1] = kreg[s].y;
                Ks[lr[s]][lc[s]+2] = kreg[s].z; Ks[lr[s]][lc[s]+3] = kreg[s].w;
                Vs[lr[s]][lc[s]+0] = vreg[s].x; Vs[lr[s]][lc[s]+1] = vreg[s].y;
                Vs[lr[s]][lc[s]+2] = vreg[s].z; Vs[lr[s]][lc[s]+3] = vreg[s].w;
            }
            __syncthreads();
        }
    }

    const float inv0 = 1.0f / l0, inv1 = 1.0f / l1;
    const int row0 = q0 + mrow + g;
    #pragma unroll
    for (int n = 0; n < 8; n++) {
        const int col = h * DKK + n * 8 + t * 2;
        *(float2*)(O + ((size_t)b * SS + row0    ) * DD + col) =
            make_float2(acc[n][0] * inv0, acc[n][1] * inv0);
        *(float2*)(O + ((size_t)b * SS + row0 + 8) * DD + col) =
            make_float2(acc[n][2] * inv1, acc[n][3] * inv1);
    }
}

// ---------------- launch ----------------------------------------------------
extern "C" void kernel_launch(void* const* d_in, const int* in_sizes, int n_in,
                              void* d_out, int out_size)
{
    const float* x     = (const float*)d_in[0];
    // d_in[1] = mask (all ones in this problem)
    const float* wq    = (const float*)d_in[2];
    const float* wk    = (const float*)d_in[3];
    const float* wv    = (const float*)d_in[4];
    const float* wo    = (const float*)d_in[5];
    const float* w1    = (const float*)d_in[6];
    const float* b1    = (const float*)d_in[7];
    const float* w2    = (const float*)d_in[8];
    const float* b2    = (const float*)d_in[9];
    const float* ln1_a = (const float*)d_in[10];
    const float* ln1_b = (const float*)d_in[11];
    const float* ln2_a = (const float*)d_in[12];
    const float* ln2_b = (const float*)d_in[13];
    float* out = (float*)d_out;

    float *xn, *q, *k, *v, *ctx, *x1, *hb;
    cudaGetSymbolAddress((void**)&xn,  g_xn);
    cudaGetSymbolAddress((void**)&q,   g_q);
    cudaGetSymbolAddress((void**)&k,   g_k);
    cudaGetSymbolAddress((void**)&v,   g_v);
    cudaGetSymbolAddress((void**)&ctx, g_ctx);
    cudaGetSymbolAddress((void**)&x1,  g_x1);
    cudaGetSymbolAddress((void**)&hb,  g_h);

    // 1) ln1
    layernorm_kernel<<<ROWS, 256>>>(x, ln1_a, ln1_b, xn);
    // 2) Q/K/V projections fused into one launch (z selects weight/output)
    gemm_tf32_kernel<<<dim3(DD / 128, ROWS / 128, 3), 256>>>(
        xn, wq, wk, wv, q, k, v, nullptr, nullptr, ROWS, DD, DD, 0);
    // 3) attention (tf32 tensor cores, pipelined K/V)
    flash_attn_tc<<<dim3(SS / 64, HH, BB), 128>>>(q, k, v, ctx);
    // 4) O projection + residual
    gemm_tf32_kernel<<<dim3(DD / 128, ROWS / 128, 1), 256>>>(
        ctx, wo, wo, wo, x1, x1, x1, nullptr, x, ROWS, DD, DD, 0);
    // 5) ln2
    layernorm_kernel<<<ROWS, 256>>>(x1, ln2_a, ln2_b, xn);
    // 6) FFN1 + bias + relu
    gemm_tf32_kernel<<<dim3(DFF / 128, ROWS / 128, 1), 256>>>(
        xn, w1, w1, w1, hb, hb, hb, b1, nullptr, ROWS, DFF, DD, 1);
    // 7) FFN2 + bias + residual -> out
    gemm_tf32_kernel<<<dim3(DD / 128, ROWS / 128, 1), 256>>>(
        hb, w2, w2, w2, out, out, out, b2, x1, ROWS, DD, DFF, 0);
}

// round 8
// speedup vs baseline: 1.1787x; 1.0133x over previous
#include <cuda_runtime.h>
#include <cuda_bf16.h>
#include <cstdint>
#include <math.h>

// Problem constants
#define BB   2
#define SS   2048
#define DD   1024
#define HH   16
#define DKK  64
#define DFF  4096
#define ROWS (BB*SS)          // 4096
#define EPS  1e-6f

// ---------------- scratch (static device memory; no allocs allowed) ----------
__device__ float g_xn [ (size_t)ROWS * DD ];
__device__ float g_q  [ (size_t)ROWS * DD ];
__device__ float g_k  [ (size_t)ROWS * DD ];
__device__ float g_v  [ (size_t)ROWS * DD ];
__device__ float g_ctx[ (size_t)ROWS * DD ];
__device__ float g_x1 [ (size_t)ROWS * DD ];
__device__ float g_h  [ (size_t)ROWS * DFF ];

// ---------------- helpers ----------------------------------------------------
__device__ __forceinline__ float to_tf32(float x) {
    unsigned int u;
    asm("cvt.rna.tf32.f32 %0, %1;" : "=r"(u) : "f"(x));
    return __uint_as_float(u);
}

__device__ __forceinline__ void mma_tf32(float* c, const unsigned int* a, const unsigned int* b) {
    asm volatile(
        "mma.sync.aligned.m16n8k8.row.col.f32.tf32.tf32.f32 "
        "{%0,%1,%2,%3}, {%4,%5,%6,%7}, {%8,%9}, {%0,%1,%2,%3};\n"
        : "+f"(c[0]), "+f"(c[1]), "+f"(c[2]), "+f"(c[3])
        : "r"(a[0]), "r"(a[1]), "r"(a[2]), "r"(a[3]),
          "r"(b[0]), "r"(b[1]));
}

// ---------------- LayerNorm: one block per row, 256 threads, float4 ---------
__global__ void layernorm_kernel(const float* __restrict__ X,
                                 const float* __restrict__ gamma,
                                 const float* __restrict__ beta,
                                 float* __restrict__ Y)
{
    __shared__ float red[8];
    const int row = blockIdx.x;
    const int tid = threadIdx.x;
    const float* x = X + (size_t)row * DD + tid * 4;

    float4 xv = *(const float4*)x;

    float s = xv.x + xv.y + xv.z + xv.w;
    #pragma unroll
    for (int o = 16; o; o >>= 1) s += __shfl_xor_sync(0xffffffffu, s, o);
    if ((tid & 31) == 0) red[tid >> 5] = s;
    __syncthreads();
    float tot = red[0] + red[1] + red[2] + red[3] + red[4] + red[5] + red[6] + red[7];
    float mean = tot * (1.0f / DD);

    float dx0 = xv.x - mean, dx1 = xv.y - mean, dx2 = xv.z - mean, dx3 = xv.w - mean;
    float sq = dx0*dx0 + dx1*dx1 + dx2*dx2 + dx3*dx3;
    __syncthreads();
    #pragma unroll
    for (int o = 16; o; o >>= 1) sq += __shfl_xor_sync(0xffffffffu, sq, o);
    if ((tid & 31) == 0) red[tid >> 5] = sq;
    __syncthreads();
    float tot2 = red[0] + red[1] + red[2] + red[3] + red[4] + red[5] + red[6] + red[7];
    float stdv = sqrtf(tot2 * (1.0f / DD));
    float inv  = 1.0f / (stdv + EPS);

    const int c = tid * 4;
    float4 g4 = *(const float4*)(gamma + c);
    float4 b4 = *(const float4*)(beta  + c);
    float4 o4;
    o4.x = g4.x * dx0 * inv + b4.x;
    o4.y = g4.y * dx1 * inv + b4.y;
    o4.z = g4.z * dx2 * inv + b4.z;
    o4.w = g4.w * dx3 * inv + b4.w;
    *(float4*)(Y + (size_t)row * DD + c) = o4;
}

// ---------------- TF32 GEMM v3: 128x256 block, 64x64 warp tiles -------------
// BM=128, BN=256, BK=16, 256 threads (8 warps, 2m x 4n), warp tile 64x64.
// Dynamic smem (54.3 KB) double-buffered; cvt.rna in load path; register
// prefetch of next tile. blockIdx.z selects among 3 (B,C) pairs (QKV fusion).
#define AST 20     // As row stride: banks (20g+t)&31 all distinct
#define BST 264    // Bs row stride: stride%32==8 => (8t+g) pattern conflict-free
#define A_FLOATS (2 * 128 * AST)   // 5120
#define B_FLOATS (2 * 16 * BST)    // 8448
#define GEMM_SMEM_BYTES ((A_FLOATS + B_FLOATS) * 4)   // 54272

__global__ void __launch_bounds__(256, 1) gemm_tf32_v3(
    const float* __restrict__ A,
    const float* __restrict__ B0, const float* __restrict__ B1, const float* __restrict__ B2,
    float* __restrict__ C0, float* __restrict__ C1, float* __restrict__ C2,
    const float* __restrict__ bias,
    const float* __restrict__ res,
    int M, int N, int K, int relu)
{
    extern __shared__ float smem[];
    float (*As)[AST] = (float(*)[AST])smem;               // [2*128][AST]
    float (*Bs)[BST] = (float(*)[BST])(smem + A_FLOATS);  // [2*16][BST]

    const float* B = (blockIdx.z == 0) ? B0 : (blockIdx.z == 1) ? B1 : B2;
    float*       C = (blockIdx.z == 0) ? C0 : (blockIdx.z == 1) ? C1 : C2;

    const int tid  = threadIdx.x;
    const int lane = tid & 31, warp = tid >> 5;
    const int wm = warp & 1;          // m half (64 rows)
    const int wn = warp >> 1;         // n quarter (64 cols)
    const int g = lane >> 2, t = lane & 3;
    const int bx = blockIdx.x, by = blockIdx.y;

    // loader mapping
    const int arow = tid >> 2;            // 0..63 (and +64)
    const int acol = (tid & 3) * 4;       // 0,4,8,12
    const int brow = tid >> 4;            // 0..15
    const int bcol = (tid & 15) * 4;      // 0..60 (and +64,+128,+192)

    const float* Ap0 = A + (size_t)(by * 128 + arow) * K + acol;
    const float* Ap1 = Ap0 + (size_t)64 * K;
    const float* Bp  = B + (size_t)brow * N + bx * 256 + bcol;

    float acc[4][8][4];
    #pragma unroll
    for (int i = 0; i < 4; i++)
        #pragma unroll
        for (int j = 0; j < 8; j++)
            #pragma unroll
            for (int e = 0; e < 4; e++) acc[i][j][e] = 0.0f;

    // prologue: tile 0 -> buffer 0
    {
        float4 a0 = *(const float4*)Ap0;
        float4 a1 = *(const float4*)Ap1;
        As[arow     ][acol+0] = to_tf32(a0.x);
        As[arow     ][acol+1] = to_tf32(a0.y);
        As[arow     ][acol+2] = to_tf32(a0.z);
        As[arow     ][acol+3] = to_tf32(a0.w);
        As[arow + 64][acol+0] = to_tf32(a1.x);
        As[arow + 64][acol+1] = to_tf32(a1.y);
        As[arow + 64][acol+2] = to_tf32(a1.z);
        As[arow + 64][acol+3] = to_tf32(a1.w);
        #pragma unroll
        for (int c = 0; c < 4; c++) {
            float4 bv = *(const float4*)(Bp + c * 64);
            Bs[brow][bcol + c*64 + 0] = to_tf32(bv.x);
            Bs[brow][bcol + c*64 + 1] = to_tf32(bv.y);
            Bs[brow][bcol + c*64 + 2] = to_tf32(bv.z);
            Bs[brow][bcol + c*64 + 3] = to_tf32(bv.w);
        }
    }
    __syncthreads();

    const int nIter = K >> 4;
    for (int it = 0; it < nIter; ++it) {
        const int cur = it & 1, nxt = cur ^ 1;
        const int abase = cur * 128, bbase = cur * 16;

        float4 na0, na1, nb[4];
        const bool pf = (it + 1 < nIter);
        if (pf) {
            const float* pa = Ap0 + (size_t)(it + 1) * 16;
            na0 = *(const float4*)pa;
            na1 = *(const float4*)(pa + (size_t)64 * K);
            const float* pb = Bp + (size_t)(it + 1) * 16 * N;
            #pragma unroll
            for (int c = 0; c < 4; c++) nb[c] = *(const float4*)(pb + c * 64);
        }

        #pragma unroll
        for (int ks = 0; ks < 2; ks++) {
            const int k0 = ks * 8;
            unsigned int af[4][4], bf[8][2];
            #pragma unroll
            for (int i = 0; i < 4; i++) {
                const int m0 = abase + wm * 64 + i * 16;
                af[i][0] = __float_as_uint(As[m0 + g    ][k0 + t    ]);
                af[i][1] = __float_as_uint(As[m0 + g + 8][k0 + t    ]);
                af[i][2] = __float_as_uint(As[m0 + g    ][k0 + t + 4]);
                af[i][3] = __float_as_uint(As[m0 + g + 8][k0 + t + 4]);
            }
            #pragma unroll
            for (int j = 0; j < 8; j++) {
                const int n0 = wn * 64 + j * 8;
                bf[j][0] = __float_as_uint(Bs[bbase + k0 + t    ][n0 + g]);
                bf[j][1] = __float_as_uint(Bs[bbase + k0 + t + 4][n0 + g]);
            }
            #pragma unroll
            for (int i = 0; i < 4; i++)
                #pragma unroll
                for (int j = 0; j < 8; j++)
                    mma_tf32(acc[i][j], af[i], bf[j]);
        }

        if (pf) {
            const int an = nxt * 128, bn = nxt * 16;
            As[an + arow     ][acol+0] = to_tf32(na0.x);
            As[an + arow     ][acol+1] = to_tf32(na0.y);
            As[an + arow     ][acol+2] = to_tf32(na0.z);
            As[an + arow     ][acol+3] = to_tf32(na0.w);
            As[an + arow + 64][acol+0] = to_tf32(na1.x);
            As[an + arow + 64][acol+1] = to_tf32(na1.y);
            As[an + arow + 64][acol+2] = to_tf32(na1.z);
            As[an + arow + 64][acol+3] = to_tf32(na1.w);
            #pragma unroll
            for (int c = 0; c < 4; c++) {
                Bs[bn + brow][bcol + c*64 + 0] = to_tf32(nb[c].x);
                Bs[bn + brow][bcol + c*64 + 1] = to_tf32(nb[c].y);
                Bs[bn + brow][bcol + c*64 + 2] = to_tf32(nb[c].z);
                Bs[bn + brow][bcol + c*64 + 3] = to_tf32(nb[c].w);
            }
        }
        __syncthreads();
    }

    // epilogue
    #pragma unroll
    for (int i = 0; i < 4; i++) {
        #pragma unroll
        for (int j = 0; j < 8; j++) {
            const int row0 = by * 128 + wm * 64 + i * 16 + g;
            const int col  = bx * 256 + wn * 64 + j * 8 + t * 2;
            float v0 = acc[i][j][0], v1 = acc[i][j][1];
            float v2 = acc[i][j][2], v3 = acc[i][j][3];
            if (bias) {
                float b0v = bias[col], b1v = bias[col + 1];
                v0 += b0v; v1 += b1v; v2 += b0v; v3 += b1v;
            }
            if (relu) {
                v0 = fmaxf(v0, 0.0f); v1 = fmaxf(v1, 0.0f);
                v2 = fmaxf(v2, 0.0f); v3 = fmaxf(v3, 0.0f);
            }
            size_t p0 = (size_t)row0 * N + col;
            size_t p1 = (size_t)(row0 + 8) * N + col;
            if (res) {
                float2 r0 = *(const float2*)(res + p0);
                float2 r1 = *(const float2*)(res + p1);
                v0 += r0.x; v1 += r0.y; v2 += r1.x; v3 += r1.y;
            }
            *(float2*)(C + p0) = make_float2(v0, v1);
            *(float2*)(C + p1) = make_float2(v2, v3);
        }
    }
}

// ---------------- Flash attention, tf32 TC + register prefetch (R6) ---------
#define FBK 32

__global__ void __launch_bounds__(128) flash_attn_tc(const float* __restrict__ Q,
                                                     const float* __restrict__ K,
                                                     const float* __restrict__ V,
                                                     float* __restrict__ O)
{
    __shared__ float Qs[64][68];
    __shared__ float Ks[FBK][68];
    __shared__ float Vs[FBK][72];
    __shared__ float Ps[64][36];

    const int b = blockIdx.z, h = blockIdx.y;
    const int q0 = blockIdx.x * 64;
    const int tid = threadIdx.x, lane = tid & 31, warp = tid >> 5;
    const int g = lane >> 2, t = lane & 3;
    const int mrow = warp * 16;

    const float* Qb = Q + ((size_t)b * SS + q0) * DD + h * DKK;
    const float* Kb = K + (size_t)b * SS * DD + h * DKK;
    const float* Vb = V + (size_t)b * SS * DD + h * DKK;

    int lr[4], lc[4];
    #pragma unroll
    for (int s = 0; s < 4; s++) {
        int i = tid + s * 128;
        lr[s] = i >> 4;
        lc[s] = (i & 15) * 4;
    }

    for (int i = tid; i < 64 * 16; i += 128) {
        int r = i >> 4, c4 = (i & 15) * 4;
        float4 qv = *(const float4*)(Qb + (size_t)r * DD + c4);
        Qs[r][c4+0] = to_tf32(qv.x);
        Qs[r][c4+1] = to_tf32(qv.y);
        Qs[r][c4+2] = to_tf32(qv.z);
        Qs[r][c4+3] = to_tf32(qv.w);
    }

    #pragma unroll
    for (int s = 0; s < 4; s++) {
        float4 kv = *(const float4*)(Kb + (size_t)lr[s] * DD + lc[s]);
        Ks[lr[s]][lc[s]+0] = kv.x; Ks[lr[s]][lc[s]+1] = kv.y;
        Ks[lr[s]][lc[s]+2] = kv.z; Ks[lr[s]][lc[s]+3] = kv.w;
        float4 vv = *(const float4*)(Vb + (size_t)lr[s] * DD + lc[s]);
        Vs[lr[s]][lc[s]+0] = vv.x; Vs[lr[s]][lc[s]+1] = vv.y;
        Vs[lr[s]][lc[s]+2] = vv.z; Vs[lr[s]][lc[s]+3] = vv.w;
    }

    float m0v = -1e30f, m1v = -1e30f, l0 = 0.0f, l1 = 0.0f;
    float acc[8][4];
    #pragma unroll
    for (int n = 0; n < 8; n++)
        #pragma unroll
        for (int e = 0; e < 4; e++) acc[n][e] = 0.0f;

    __syncthreads();

    for (int k0 = 0; k0 < SS; k0 += FBK) {
        const bool pf = (k0 + FBK < SS);
        float4 kreg[4], vreg[4];
        if (pf) {
            const float* Kn = Kb + (size_t)(k0 + FBK) * DD;
            const float* Vn = Vb + (size_t)(k0 + FBK) * DD;
            #pragma unroll
            for (int s = 0; s < 4; s++) {
                kreg[s] = *(const float4*)(Kn + (size_t)lr[s] * DD + lc[s]);
                vreg[s] = *(const float4*)(Vn + (size_t)lr[s] * DD + lc[s]);
            }
        }

        float sf[4][4];
        #pragma unroll
        for (int j = 0; j < 4; j++)
            #pragma unroll
            for (int e = 0; e < 4; e++) sf[j][e] = 0.0f;

        #pragma unroll
        for (int kc = 0; kc < 8; kc++) {
            const int kk = kc * 8;
            unsigned int af[4];
            af[0] = __float_as_uint(Qs[mrow + g    ][kk + t    ]);
            af[1] = __float_as_uint(Qs[mrow + g + 8][kk + t    ]);
            af[2] = __float_as_uint(Qs[mrow + g    ][kk + t + 4]);
            af[3] = __float_as_uint(Qs[mrow + g + 8][kk + t + 4]);
            #pragma unroll
            for (int j = 0; j < 4; j++) {
                unsigned int bf[2];
                bf[0] = __float_as_uint(Ks[j * 8 + g][kk + t    ]);
                bf[1] = __float_as_uint(Ks[j * 8 + g][kk + t + 4]);
                mma_tf32(sf[j], af, bf);
            }
        }

        float rmax0 = -1e30f, rmax1 = -1e30f;
        #pragma unroll
        for (int j = 0; j < 4; j++) {
            sf[j][0] *= 0.125f; sf[j][1] *= 0.125f;
            sf[j][2] *= 0.125f; sf[j][3] *= 0.125f;
            rmax0 = fmaxf(rmax0, fmaxf(sf[j][0], sf[j][1]));
            rmax1 = fmaxf(rmax1, fmaxf(sf[j][2], sf[j][3]));
        }
        rmax0 = fmaxf(rmax0, __shfl_xor_sync(0xffffffffu, rmax0, 1));
        rmax0 = fmaxf(rmax0, __shfl_xor_sync(0xffffffffu, rmax0, 2));
        rmax1 = fmaxf(rmax1, __shfl_xor_sync(0xffffffffu, rmax1, 1));
        rmax1 = fmaxf(rmax1, __shfl_xor_sync(0xffffffffu, rmax1, 2));

        float mn0 = fmaxf(m0v, rmax0), mn1 = fmaxf(m1v, rmax1);
        float c0 = __expf(m0v - mn0), c1 = __expf(m1v - mn1);
        m0v = mn0; m1v = mn1;

        float ps0 = 0.0f, ps1 = 0.0f;
        #pragma unroll
        for (int j = 0; j < 4; j++) {
            float p00 = __expf(sf[j][0] - mn0);
            float p01 = __expf(sf[j][1] - mn0);
            float p10 = __expf(sf[j][2] - mn1);
            float p11 = __expf(sf[j][3] - mn1);
            ps0 += p00 + p01;
            ps1 += p10 + p11;
            *(float2*)&Ps[mrow + g    ][j * 8 + t * 2] = make_float2(to_tf32(p00), to_tf32(p01));
            *(float2*)&Ps[mrow + g + 8][j * 8 + t * 2] = make_float2(to_tf32(p10), to_tf32(p11));
        }
        ps0 += __shfl_xor_sync(0xffffffffu, ps0, 1);
        ps0 += __shfl_xor_sync(0xffffffffu, ps0, 2);
        ps1 += __shfl_xor_sync(0xffffffffu, ps1, 1);
        ps1 += __shfl_xor_sync(0xffffffffu, ps1, 2);
        l0 = l0 * c0 + ps0;
        l1 = l1 * c1 + ps1;

        #pragma unroll
        for (int n = 0; n < 8; n++) {
            acc[n][0] *= c0; acc[n][1] *= c0;
            acc[n][2] *= c1; acc[n][3] *= c1;
        }
        __syncwarp();

        #pragma unroll
        for (int kc = 0; kc < 4; kc++) {
            const int kk = kc * 8;
            unsigned int af[4];
            af[0] = __float_as_uint(Ps[mrow + g    ][kk + t    ]);
            af[1] = __float_as_uint(Ps[mrow + g + 8][kk + t    ]);
            af[2] = __float_as_uint(Ps[mrow + g    ][kk + t + 4]);
            af[3] = __float_as_uint(Ps[mrow + g + 8][kk + t + 4]);
            #pragma unroll
            for (int n = 0; n < 8; n++) {
                unsigned int bf[2];
                bf[0] = __float_as_uint(Vs[kk + t    ][n * 8 + g]);
                bf[1] = __float_as_uint(Vs[kk + t + 4][n * 8 + g]);
                mma_tf32(acc[n], af, bf);
            }
        }

        __syncthreads();
        if (pf) {
            #pragma unroll
            for (int s = 0; s < 4; s++) {
                Ks[lr[s]][lc[s]+0] = kreg[s].x; Ks[lr[s]][lc[s]+1] = kreg[s].y;
                Ks[lr[s]][lc[s]+2] = kreg[s].z; Ks[lr[s]][lc[s]+3] = kreg[s].w;
                Vs[lr[s]][lc[s]+0] = vreg[s].x; Vs[lr[s]][lc[s]+1] = vreg[s].y;
                Vs[lr[s]][lc[s]+2] = vreg[s].z; Vs[lr[s]][lc[s]+3] = vreg[s].w;
            }
            __syncthreads();
        }
    }

    const float inv0 = 1.0f / l0, inv1 = 1.0f / l1;
    const int row0 = q0 + mrow + g;
    #pragma unroll
    for (int n = 0; n < 8; n++) {
        const int col = h * DKK + n * 8 + t * 2;
        *(float2*)(O + ((size_t)b * SS + row0    ) * DD + col) =
            make_float2(acc[n][0] * inv0, acc[n][1] * inv0);
        *(float2*)(O + ((size_t)b * SS + row0 + 8) * DD + col) =
            make_float2(acc[n][2] * inv1, acc[n][3] * inv1);
    }
}

// ---------------- launch ----------------------------------------------------
extern "C" void kernel_launch(void* const* d_in, const int* in_sizes, int n_in,
                              void* d_out, int out_size)
{
    const float* x     = (const float*)d_in[0];
    // d_in[1] = mask (all ones in this problem)
    const float* wq    = (const float*)d_in[2];
    const float* wk    = (const float*)d_in[3];
    const float* wv    = (const float*)d_in[4];
    const float* wo    = (const float*)d_in[5];
    const float* w1    = (const float*)d_in[6];
    const float* b1    = (const float*)d_in[7];
    const float* w2    = (const float*)d_in[8];
    const float* b2    = (const float*)d_in[9];
    const float* ln1_a = (const float*)d_in[10];
    const float* ln1_b = (const float*)d_in[11];
    const float* ln2_a = (const float*)d_in[12];
    const float* ln2_b = (const float*)d_in[13];
    float* out = (float*)d_out;

    float *xn, *q, *k, *v, *ctx, *x1, *hb;
    cudaGetSymbolAddress((void**)&xn,  g_xn);
    cudaGetSymbolAddress((void**)&q,   g_q);
    cudaGetSymbolAddress((void**)&k,   g_k);
    cudaGetSymbolAddress((void**)&v,   g_v);
    cudaGetSymbolAddress((void**)&ctx, g_ctx);
    cudaGetSymbolAddress((void**)&x1,  g_x1);
    cudaGetSymbolAddress((void**)&hb,  g_h);

    static bool attr_done = false;
    if (!attr_done) {
        cudaFuncSetAttribute(gemm_tf32_v3,
                             cudaFuncAttributeMaxDynamicSharedMemorySize,
                             GEMM_SMEM_BYTES);
        attr_done = true;
    }

    // 1) ln1
    layernorm_kernel<<<ROWS, 256>>>(x, ln1_a, ln1_b, xn);
    // 2) Q/K/V projections fused into one launch (z selects weight/output)
    gemm_tf32_v3<<<dim3(DD / 256, ROWS / 128, 3), 256, GEMM_SMEM_BYTES>>>(
        xn, wq, wk, wv, q, k, v, nullptr, nullptr, ROWS, DD, DD, 0);
    // 3) attention (tf32 tensor cores, pipelined K/V)
    flash_attn_tc<<<dim3(SS / 64, HH, BB), 128>>>(q, k, v, ctx);
    // 4) O projection + residual
    gemm_tf32_v3<<<dim3(DD / 256, ROWS / 128, 1), 256, GEMM_SMEM_BYTES>>>(
        ctx, wo, wo, wo, x1, x1, x1, nullptr, x, ROWS, DD, DD, 0);
    // 5) ln2
    layernorm_kernel<<<ROWS, 256>>>(x1, ln2_a, ln2_b, xn);
    // 6) FFN1 + bias + relu
    gemm_tf32_v3<<<dim3(DFF / 256, ROWS / 128, 1), 256, GEMM_SMEM_BYTES>>>(
        xn, w1, w1, w1, hb, hb, hb, b1, nullptr, ROWS, DFF, DD, 1);
    // 7) FFN2 + bias + residual -> out
    gemm_tf32_v3<<<dim3(DD / 256, ROWS / 128, 1), 256, GEMM_SMEM_BYTES>>>(
        hb, w2, w2, w2, out, out, out, b2, x1, ROWS, DD, DFF, 0);
}